// round 6
// baseline (speedup 1.0000x reference)
#include <cuda_runtime.h>
#include <math.h>

#define NN 1024
#define MM 64
#define LDA 1040          // row stride of cov scratch (floats)
#define GLD 1056          // row stride of k-major panel buffer (floats)
#define NTH 512

__device__ float g_cov[(size_t)MM * NN * LDA];
__device__ float g_pt_[(size_t)MM * 64 * GLD];   // k-major solved panel, per matrix

typedef unsigned long long ull;

__device__ __forceinline__ ull pack2(float lo, float hi) {
    ull r; asm("mov.b64 %0, {%1, %2};" : "=l"(r) : "f"(lo), "f"(hi)); return r;
}
__device__ __forceinline__ void fma2(ull& d, ull a, ull b) {
    asm("fma.rn.f32x2 %0, %1, %2, %0;" : "+l"(d) : "l"(a), "l"(b));
}
__device__ __forceinline__ float2 unpack2(ull v) {
    float2 f; asm("mov.b64 {%0, %1}, %2;" : "=f"(f.x), "=f"(f.y) : "l"(v)); return f;
}
__device__ __forceinline__ void cluster_sync_() {
    asm volatile("barrier.cluster.arrive.aligned;" ::: "memory");
    asm volatile("barrier.cluster.wait.aligned;" ::: "memory");
}

__device__ __forceinline__ float sp_(float x) {
    return fmaxf(x, 0.f) + log1pf(expf(-fabsf(x))) + 1e-7f;
}
__device__ __forceinline__ float log_normal_(float v, float mean, float s, float eps) {
    const float C = -0.91893853320467274178f;
    float d = v - mean;
    return -d * d / (2.f * s * s + eps) - logf(s) + C;
}
__device__ __forceinline__ float log_lognormal_(float v, float mean, float s, float eps) {
    const float C = -0.91893853320467274178f;
    float lv = logf(v);
    float d = lv - mean;
    return -d * d / (2.f * s * s + eps) - lv - logf(s) + C;
}

// 32x32 lower-tri solve of one row vector a[32] against factored Lkk/rinv
__device__ __forceinline__ void trsm_row(float* a, const float* Lkk, const float* rinv) {
    #pragma unroll
    for (int j = 0; j < 32; ++j) {
        float s = a[j];
        #pragma unroll
        for (int p = 0; p < j; ++p)
            s -= a[p] * Lkk[j * 33 + p];
        a[j] = s * rinv[j];
    }
}

extern "C" __global__ void __launch_bounds__(NTH, 1) __cluster_dims__(2, 1, 1)
vi_kernel(const float* __restrict__ x, const float* __restrict__ y,
          const float* __restrict__ z,
          const float* qbm, const float* qbs, const float* qsm, const float* qss,
          const float* qem, const float* qes, const float* qzm, const float* qzs,
          const float* qnm, const float* qns, float* __restrict__ out)
{
    __shared__ float xs[2048];          // scaled x (build); rhs (fwd-subst)
    __shared__ float Lkk[32 * 33];
    __shared__ float Bb[32 * 33];
    __shared__ float rinv[32];
    __shared__ float scal[8];
    __shared__ float red[NTH];

    const int tid  = threadIdx.x;
    const int m    = blockIdx.x >> 1;
    const int rank = blockIdx.x & 1;
    float* cov = g_cov + (size_t)m * NN * LDA;
    float* gpt = g_pt_ + (size_t)m * 64 * GLD;

    // ---- scalar terms (thread 0 of each CTA, redundant) ----
    if (tid == 0) {
        float s0 = sp_(sqrtf(logf(2.f)));
        float z0 = z[m * 5 + 0], z1 = z[m * 5 + 1], z2 = z[m * 5 + 2];
        float z3 = z[m * 5 + 3], z4 = z[m * 5 + 4];
        float sps = sp_(*qss), spb = sp_(*qbs), spe = sp_(*qes);
        float spz = sp_(*qzs), spn = sp_(*qns);
        float sigma2 = expf(z0 * sps + *qsm);
        float beta   = z1 * spb + *qbm;
        float eta    = expf(z2 * spe + *qem);
        float lsZ    = expf(z3 * spz + *qzm);
        float lsN    = expf(z4 * spn + *qnm);
        float lp = log_normal_(beta, 0.f, 1.f, 1e-5f)
                 + log_lognormal_(sigma2, 1.f, s0, 1e-6f)
                 + log_lognormal_(eta,    1.f, s0, 1e-6f)
                 + log_lognormal_(lsZ,    1.f, s0, 1e-6f)
                 + log_lognormal_(lsN,    1.f, s0, 1e-6f);
        float lq = log_normal_(beta, *qbm, spb, 1e-5f)
                 + log_lognormal_(sigma2, *qsm, sps, 1e-6f)
                 + log_lognormal_(eta,    *qem, spe, 1e-6f)
                 + log_lognormal_(lsZ,    *qzm, spz, 1e-6f)
                 + log_lognormal_(lsN,    *qnm, spn, 1e-6f);
        scal[0] = beta; scal[1] = sigma2; scal[2] = eta;
        scal[3] = lsZ;  scal[4] = lsN;    scal[5] = lp - lq;
        scal[6] = 0.f;
    }
    __syncthreads();
    const float beta = scal[0], sigma2 = scal[1], eta = scal[2];

    // ---- stage scaled x into smem ----
    {
        float lsZ = scal[3], lsN = scal[4];
        for (int i = tid; i < NN; i += NTH) {
            xs[i]        = x[2 * i]     / lsZ;
            xs[NN + i]   = x[2 * i + 1] / lsN;
        }
    }
    __syncthreads();

    // ---- build lower-triangular cov, rows split by parity, vectorized ----
    {
        const float* xs0 = xs;
        const float* xs1 = xs + NN;
        for (int it = tid; it < NN / 2; it += NTH) {
            int i = 2 * it + rank;
            float xi0 = xs0[i], xi1 = xs1[i];
            float* row = cov + (size_t)i * LDA;
            int j4 = i & ~3;
            for (int j = 0; j < j4; j += 4) {
                float4 a0 = *(const float4*)(xs0 + j);
                float4 a1 = *(const float4*)(xs1 + j);
                float4 o;
                float d0, d1;
                d0 = xi0 - a0.x; d1 = xi1 - a1.x; o.x = eta * __expf(-0.5f * (d0*d0 + d1*d1));
                d0 = xi0 - a0.y; d1 = xi1 - a1.y; o.y = eta * __expf(-0.5f * (d0*d0 + d1*d1));
                d0 = xi0 - a0.z; d1 = xi1 - a1.z; o.z = eta * __expf(-0.5f * (d0*d0 + d1*d1));
                d0 = xi0 - a0.w; d1 = xi1 - a1.w; o.w = eta * __expf(-0.5f * (d0*d0 + d1*d1));
                *(float4*)(row + j) = o;
            }
            for (int j = j4; j < i; ++j) {
                float d0 = xi0 - xs0[j];
                float d1 = xi1 - xs1[j];
                row[j] = eta * __expf(-0.5f * (d0 * d0 + d1 * d1));
            }
            row[i] = eta + sigma2;
        }
    }
    cluster_sync_();

    // ---- blocked Cholesky: outer NB=64 (16 steps), inner 32-panels ----
    for (int kb = 0; kb < 16; ++kb) {
        const int k0 = kb * 64;
        const int R1 = NN - k0 - 32;          // panel1 rows (start k0+32)
        const int nt = NN - k0 - 64;          // trailing size (start k0+64)

        // ===== phase 1: diag1 + panel1 (cols k0..k0+31) =====
        // load raw diag1 into Lkk
        for (int idx = tid; idx < 1024; idx += NTH) {
            int r = idx >> 5, c = idx & 31;
            Lkk[r * 33 + c] = (c <= r) ? cov[(size_t)(k0 + r) * LDA + k0 + c] : 0.f;
        }
        // contiguous-half split of panel rows
        const int h1len = (R1 + 1) >> 1;
        const int h1s = rank * h1len;
        const int h1e = (rank == 0) ? h1len : R1;
        float a1[32];
        const int r1 = h1s + tid - 32;
        const bool pv1 = (tid >= 32) && (r1 < h1e);
        if (pv1) {
            const float* rr = cov + (size_t)(k0 + 32 + r1) * LDA + k0;
            #pragma unroll
            for (int w = 0; w < 8; ++w) {
                float4 q = ((const float4*)rr)[w];
                a1[4*w] = q.x; a1[4*w+1] = q.y; a1[4*w+2] = q.z; a1[4*w+3] = q.w;
            }
        }
        __syncthreads();

        // warp 0: factor diag1
        if (tid < 32) {
            const int lane = tid;
            float a[32];
            #pragma unroll
            for (int j = 0; j < 32; ++j) a[j] = Lkk[lane * 33 + j];
            #pragma unroll
            for (int j = 0; j < 32; ++j) {
                float dj = __shfl_sync(0xffffffffu, a[j], j);
                float sj = sqrtf(dj);
                float lrj = (lane == j) ? sj : a[j] / sj;
                a[j] = lrj;
                #pragma unroll
                for (int c = j + 1; c < 32; ++c) {
                    float lcj = __shfl_sync(0xffffffffu, lrj, c);
                    a[c] -= lrj * lcj;
                }
            }
            #pragma unroll
            for (int j = 0; j < 32; ++j)
                if (j <= lane) Lkk[lane * 33 + j] = a[j];
            rinv[lane] = 1.f / a[lane];
            float ld = logf(a[lane]);
            #pragma unroll
            for (int o = 16; o; o >>= 1) ld += __shfl_xor_sync(0xffffffffu, ld, o);
            if (lane == 0) scal[6] += ld;
        }
        __syncthreads();

        // warp0/rank0 writes diag1 back; panel threads TRSM + write
        if (tid < 32) {
            if (rank == 0) {
                float* wr = cov + (size_t)(k0 + tid) * LDA + k0;
                for (int j = 0; j <= tid; ++j) wr[j] = Lkk[tid * 33 + j];
            }
        } else if (pv1) {
            trsm_row(a1, Lkk, rinv);
            float* wr = cov + (size_t)(k0 + 32 + r1) * LDA + k0;
            #pragma unroll
            for (int w = 0; w < 8; ++w)
                ((float4*)wr)[w] = make_float4(a1[4*w], a1[4*w+1], a1[4*w+2], a1[4*w+3]);
            if (r1 >= 32) {
                const int ic = r1 - 32;   // trailing-relative column
                #pragma unroll
                for (int p = 0; p < 32; ++p) gpt[p * GLD + ic] = a1[p];
            }
        }
        // leftover rows (only kb==0: half=496 > 480 worker threads)
        {
            int rb = h1s + 480 + (tid - 32);
            if (tid >= 32 && tid < 48 && rb < h1e) {
                const float* rr = cov + (size_t)(k0 + 32 + rb) * LDA + k0;
                #pragma unroll
                for (int w = 0; w < 8; ++w) {
                    float4 q = ((const float4*)rr)[w];
                    a1[4*w] = q.x; a1[4*w+1] = q.y; a1[4*w+2] = q.z; a1[4*w+3] = q.w;
                }
                trsm_row(a1, Lkk, rinv);
                float* wr = cov + (size_t)(k0 + 32 + rb) * LDA + k0;
                #pragma unroll
                for (int w = 0; w < 8; ++w)
                    ((float4*)wr)[w] = make_float4(a1[4*w], a1[4*w+1], a1[4*w+2], a1[4*w+3]);
                if (rb >= 32) {
                    const int ic = rb - 32;
                    #pragma unroll
                    for (int p = 0; p < 32; ++p) gpt[p * GLD + ic] = a1[p];
                }
            }
        }
        cluster_sync_();   // A: all panel1 rows solved + visible

        // ===== phase 2: diag2 + narrow update + panel2 (cols k0+32..63) =====
        // Bb = solved rows k0+32..63, cols k0..31
        for (int idx = tid; idx < 1024; idx += NTH) {
            int r = idx >> 5, c = idx & 31;
            Bb[r * 33 + c] = cov[(size_t)(k0 + 32 + r) * LDA + k0 + c];
        }
        // prefetch panel2 row pieces
        const int h2len = (nt + 1) >> 1;
        const int h2s = rank * h2len;
        const int h2e = (rank == 0) ? h2len : nt;
        float A32[32], w2[32];
        const int r2 = h2s + tid - 32;
        const bool pv2 = (tid >= 32) && (r2 < h2e) && (nt > 0);
        if (pv2) {
            const float* rr = cov + (size_t)(k0 + 64 + r2) * LDA + k0;
            #pragma unroll
            for (int w = 0; w < 8; ++w) {
                float4 qa = ((const float4*)rr)[w];
                float4 qb = ((const float4*)(rr + 32))[w];
                A32[4*w] = qa.x; A32[4*w+1] = qa.y; A32[4*w+2] = qa.z; A32[4*w+3] = qa.w;
                w2[4*w]  = qb.x; w2[4*w+1]  = qb.y; w2[4*w+2]  = qb.z; w2[4*w+3]  = qb.w;
            }
        }
        __syncthreads();   // Bb ready

        // diag2 adjust: Lkk = raw diag2 - Bb*Bb^T (lower)
        for (int idx = tid; idx < 1024; idx += NTH) {
            int r = idx >> 5, c = idx & 31;
            float v = 0.f;
            if (c <= r) {
                v = cov[(size_t)(k0 + 32 + r) * LDA + k0 + 32 + c];
                #pragma unroll
                for (int p = 0; p < 32; ++p)
                    v -= Bb[r * 33 + p] * Bb[c * 33 + p];
            }
            Lkk[r * 33 + c] = v;
        }
        __syncthreads();

        // warp0 factors diag2; other threads do narrow update concurrently
        if (tid < 32) {
            const int lane = tid;
            float a[32];
            #pragma unroll
            for (int j = 0; j < 32; ++j) a[j] = Lkk[lane * 33 + j];
            #pragma unroll
            for (int j = 0; j < 32; ++j) {
                float dj = __shfl_sync(0xffffffffu, a[j], j);
                float sj = sqrtf(dj);
                float lrj = (lane == j) ? sj : a[j] / sj;
                a[j] = lrj;
                #pragma unroll
                for (int c = j + 1; c < 32; ++c) {
                    float lcj = __shfl_sync(0xffffffffu, lrj, c);
                    a[c] -= lrj * lcj;
                }
            }
            #pragma unroll
            for (int j = 0; j < 32; ++j)
                if (j <= lane) Lkk[lane * 33 + j] = a[j];
            rinv[lane] = 1.f / a[lane];
            float ld = logf(a[lane]);
            #pragma unroll
            for (int o = 16; o; o >>= 1) ld += __shfl_xor_sync(0xffffffffu, ld, o);
            if (lane == 0) scal[6] += ld;
            if (rank == 0) {
                float* wr = cov + (size_t)(k0 + 32 + lane) * LDA + k0 + 32;
                for (int j = 0; j <= lane; ++j) wr[j] = Lkk[lane * 33 + j];
            }
        } else if (pv2) {
            // narrow update: w2 -= A32 * Bb^T   (independent of diag2 factor)
            #pragma unroll
            for (int c = 0; c < 32; ++c) {
                float s = w2[c];
                #pragma unroll
                for (int p = 0; p < 32; ++p)
                    s -= A32[p] * Bb[c * 33 + p];
                w2[c] = s;
            }
        }
        __syncthreads();

        if (pv2) {
            trsm_row(w2, Lkk, rinv);
            float* wr = cov + (size_t)(k0 + 64 + r2) * LDA + k0 + 32;
            #pragma unroll
            for (int w = 0; w < 8; ++w)
                ((float4*)wr)[w] = make_float4(w2[4*w], w2[4*w+1], w2[4*w+2], w2[4*w+3]);
            #pragma unroll
            for (int p = 0; p < 32; ++p) gpt[(32 + p) * GLD + r2] = w2[p];
        }
        cluster_sync_();   // B: full K=64 panel in gpt

        // ===== phase 3: trailing K=64 update from gpt (L1-cached LDG) =====
        if (nt > 0) {
            const int ntile = (nt + 127) >> 7;
            const int npair = ntile * (ntile + 1) / 2;
            const int grp = rank * 2 + (tid >> 8);
            const int t   = tid & 255;
            const int tx = t & 15, ty = t >> 4;
            for (int pair = grp; pair < npair; pair += 4) {
                int tjb = 0, rem = pair;
                while (rem >= ntile - tjb) { rem -= ntile - tjb; ++tjb; }
                int tib = tjb + rem;

                const int il = tib * 128 + ty * 8;
                const int jl = tjb * 128 + tx * 8;
                ull acc[8][4];
                #pragma unroll
                for (int r = 0; r < 8; ++r)
                    #pragma unroll
                    for (int s = 0; s < 4; ++s) acc[r][s] = 0ull;

                const float* gpA = gpt + il;
                const float* gpB = gpt + jl;
                #pragma unroll 4
                for (int p = 0; p < 64; ++p) {
                    float4 av0 = *(const float4*)(gpA + p * GLD);
                    float4 av1 = *(const float4*)(gpA + p * GLD + 4);
                    float4 bv0 = *(const float4*)(gpB + p * GLD);
                    float4 bv1 = *(const float4*)(gpB + p * GLD + 4);
                    ull b2[4] = { pack2(bv0.x, bv0.y), pack2(bv0.z, bv0.w),
                                  pack2(bv1.x, bv1.y), pack2(bv1.z, bv1.w) };
                    float aa[8] = { av0.x, av0.y, av0.z, av0.w,
                                    av1.x, av1.y, av1.z, av1.w };
                    #pragma unroll
                    for (int r = 0; r < 8; ++r) {
                        ull a2d = pack2(aa[r], aa[r]);
                        fma2(acc[r][0], a2d, b2[0]);
                        fma2(acc[r][1], a2d, b2[1]);
                        fma2(acc[r][2], a2d, b2[2]);
                        fma2(acc[r][3], a2d, b2[3]);
                    }
                }
                const int g0 = k0 + 64;
                #pragma unroll
                for (int r = 0; r < 8; ++r) {
                    const int i = il + r;
                    if (i < nt) {
                        float* row = cov + (size_t)(g0 + i) * LDA + g0;
                        if (jl + 7 <= i && jl + 7 < nt) {
                            float4 c0 = *(float4*)(row + jl);
                            float4 c1 = *(float4*)(row + jl + 4);
                            float2 u;
                            u = unpack2(acc[r][0]); c0.x -= u.x; c0.y -= u.y;
                            u = unpack2(acc[r][1]); c0.z -= u.x; c0.w -= u.y;
                            u = unpack2(acc[r][2]); c1.x -= u.x; c1.y -= u.y;
                            u = unpack2(acc[r][3]); c1.z -= u.x; c1.w -= u.y;
                            *(float4*)(row + jl)     = c0;
                            *(float4*)(row + jl + 4) = c1;
                        } else {
                            #pragma unroll
                            for (int s = 0; s < 4; ++s) {
                                float2 u = unpack2(acc[r][s]);
                                int j = jl + 2 * s;
                                if (j     <= i && j     < nt) row[j]     -= u.x;
                                if (j + 1 <= i && j + 1 < nt) row[j + 1] -= u.y;
                            }
                        }
                    }
                }
            }
        }
        cluster_sync_();   // C: trailing fully updated
    }

    // ---- forward substitution + output: rank 0 only ----
    if (rank != 0) return;

    float* rhs = xs;
    for (int i = tid; i < NN; i += NTH) rhs[i] = y[i] - beta;
    __syncthreads();

    for (int kb = 0; kb < 32; ++kb) {
        const int k0 = kb * 32;
        if (tid < 32) {
            const int lane = tid;
            const float* lrow = cov + (size_t)(k0 + lane) * LDA + k0;
            float lr[32];
            #pragma unroll
            for (int w = 0; w < 8; ++w) {
                float4 q = ((const float4*)lrow)[w];
                lr[4*w] = q.x; lr[4*w+1] = q.y; lr[4*w+2] = q.z; lr[4*w+3] = q.w;
            }
            float t = rhs[k0 + lane];
            #pragma unroll
            for (int j = 0; j < 32; ++j) {
                if (lane == j) t /= lr[j];
                float sj = __shfl_sync(0xffffffffu, t, j);
                if (lane > j) t -= sj * lr[j];
            }
            rhs[k0 + lane] = t;
        }
        __syncthreads();
        for (int i = k0 + 32 + tid; i < NN; i += NTH) {
            const float* row = cov + (size_t)i * LDA + k0;
            float acc = 0.f;
            #pragma unroll
            for (int w = 0; w < 8; ++w) {
                float4 c4 = ((const float4*)row)[w];
                acc += c4.x * rhs[k0 + 4*w]     + c4.y * rhs[k0 + 4*w + 1]
                     + c4.z * rhs[k0 + 4*w + 2] + c4.w * rhs[k0 + 4*w + 3];
            }
            rhs[i] -= acc;
        }
        __syncthreads();
    }

    float q = 0.f;
    for (int i = tid; i < NN; i += NTH) { float v = rhs[i]; q += v * v; }
    red[tid] = q;
    __syncthreads();
    for (int s = NTH / 2; s; s >>= 1) {
        if (tid < s) red[tid] += red[tid + s];
        __syncthreads();
    }
    if (tid == 0) {
        float logdet = 2.f * scal[6];
        const float LN2PI = 1.8378770664093453f;
        float ll = -0.5f * (red[0] + logdet + 1024.f * LN2PI);
        out[m] = ll + scal[5];
    }
}

extern "C" void kernel_launch(void* const* d_in, const int* in_sizes, int n_in,
                              void* d_out, int out_size)
{
    (void)in_sizes; (void)n_in; (void)out_size;
    const float* x = (const float*)d_in[0];
    const float* y = (const float*)d_in[1];
    const float* z = (const float*)d_in[2];

    vi_kernel<<<2 * MM, NTH>>>(
        x, y, z,
        (const float*)d_in[3], (const float*)d_in[4],
        (const float*)d_in[5], (const float*)d_in[6],
        (const float*)d_in[7], (const float*)d_in[8],
        (const float*)d_in[9], (const float*)d_in[10],
        (const float*)d_in[11], (const float*)d_in[12],
        (float*)d_out);
}

// round 9
// speedup vs baseline: 1.0985x; 1.0985x over previous
#include <cuda_runtime.h>
#include <cuda_bf16.h>
#include <math.h>
#include <stdint.h>

#define NN 1024
#define MM 64
#define LDA 1040
#define NTH 512
#define PH 36              // bf16 pitch of panel planes (72B rows)

__device__ float g_cov[(size_t)MM * NN * LDA];

// smem (floats): planes H,L (u32 36864) | Lkk 1056 | rinv 32 | scal 8 | red 512
#define OFF_LKK  36864
#define OFF_RINV (OFF_LKK + 1056)
#define OFF_SCAL (OFF_RINV + 32)
#define OFF_RED  (OFF_SCAL + 8)
#define SMEM_FLOATS (OFF_RED + NTH)

__device__ __forceinline__ void cluster_sync_() {
    asm volatile("barrier.cluster.arrive.aligned;" ::: "memory");
    asm volatile("barrier.cluster.wait.aligned;" ::: "memory");
}
__device__ __forceinline__ void hmma(float* c, const uint32_t* a, const uint32_t* b) {
    asm volatile("mma.sync.aligned.m16n8k16.row.col.f32.bf16.bf16.f32 "
        "{%0,%1,%2,%3},{%4,%5,%6,%7},{%8,%9},{%0,%1,%2,%3};"
        : "+f"(c[0]), "+f"(c[1]), "+f"(c[2]), "+f"(c[3])
        : "r"(a[0]), "r"(a[1]), "r"(a[2]), "r"(a[3]), "r"(b[0]), "r"(b[1]));
}

__device__ __forceinline__ float sp_(float x) {
    return fmaxf(x, 0.f) + log1pf(expf(-fabsf(x))) + 1e-7f;
}
__device__ __forceinline__ float log_normal_(float v, float mean, float s, float eps) {
    const float C = -0.91893853320467274178f;
    float d = v - mean;
    return -d * d / (2.f * s * s + eps) - logf(s) + C;
}
__device__ __forceinline__ float log_lognormal_(float v, float mean, float s, float eps) {
    const float C = -0.91893853320467274178f;
    float lv = logf(v);
    float d = lv - mean;
    return -d * d / (2.f * s * s + eps) - lv - logf(s) + C;
}
__device__ __forceinline__ void trsm_row(float* a, const float* Lkk, const float* rinv) {
    #pragma unroll
    for (int j = 0; j < 32; ++j) {
        float s = a[j];
        #pragma unroll
        for (int p = 0; p < j; ++p) s -= a[p] * Lkk[j * 33 + p];
        a[j] = s * rinv[j];
    }
}

// store one solved 32-wide row into bf16 hi/lo planes (i-major, pitch PH)
__device__ __forceinline__ void panel_store_row(uint16_t* Hb, uint16_t* Lb, int r, const float* a) {
    uint32_t hw[16], lw[16];
    #pragma unroll
    for (int q = 0; q < 16; ++q) {
        float f0 = a[2*q], f1 = a[2*q+1];
        __nv_bfloat16 h0 = __float2bfloat16(f0);
        __nv_bfloat16 h1 = __float2bfloat16(f1);
        __nv_bfloat16 l0 = __float2bfloat16(f0 - __bfloat162float(h0));
        __nv_bfloat16 l1 = __float2bfloat16(f1 - __bfloat162float(h1));
        hw[q] = (uint32_t)__bfloat16_as_ushort(h0) | ((uint32_t)__bfloat16_as_ushort(h1) << 16);
        lw[q] = (uint32_t)__bfloat16_as_ushort(l0) | ((uint32_t)__bfloat16_as_ushort(l1) << 16);
    }
    uint32_t* hr = (uint32_t*)(Hb + r * PH);
    uint32_t* lr = (uint32_t*)(Lb + r * PH);
    #pragma unroll
    for (int q = 0; q < 8; ++q) {
        *(uint2*)(hr + 2*q) = make_uint2(hw[2*q], hw[2*q+1]);
        *(uint2*)(lr + 2*q) = make_uint2(lw[2*q], lw[2*q+1]);
    }
}

extern "C" __global__ void __launch_bounds__(NTH, 1) __cluster_dims__(2, 1, 1)
vi_kernel(const float* __restrict__ x, const float* __restrict__ y,
          const float* __restrict__ z,
          const float* qbm, const float* qbs, const float* qsm, const float* qss,
          const float* qem, const float* qes, const float* qzm, const float* qzs,
          const float* qnm, const float* qns, float* __restrict__ out)
{
    extern __shared__ float sm[];
    uint16_t* Hb = (uint16_t*)sm;
    uint16_t* Lb = Hb + 1024 * PH;
    float* Lkk  = sm + OFF_LKK;
    float* rinv = sm + OFF_RINV;
    float* scal = sm + OFF_SCAL;
    float* red  = sm + OFF_RED;

    const int tid  = threadIdx.x;
    const int wid  = tid >> 5;
    const int lane = tid & 31;
    const int m    = blockIdx.x >> 1;
    const int rank = blockIdx.x & 1;
    float* cov = g_cov + (size_t)m * NN * LDA;

    // ---- scalar terms ----
    if (tid == 0) {
        float s0 = sp_(sqrtf(logf(2.f)));
        float z0 = z[m*5+0], z1 = z[m*5+1], z2 = z[m*5+2], z3 = z[m*5+3], z4 = z[m*5+4];
        float sps = sp_(*qss), spb = sp_(*qbs), spe = sp_(*qes), spz = sp_(*qzs), spn = sp_(*qns);
        float sigma2 = expf(z0 * sps + *qsm);
        float beta   = z1 * spb + *qbm;
        float eta    = expf(z2 * spe + *qem);
        float lsZ    = expf(z3 * spz + *qzm);
        float lsN    = expf(z4 * spn + *qnm);
        float lp = log_normal_(beta, 0.f, 1.f, 1e-5f)
                 + log_lognormal_(sigma2, 1.f, s0, 1e-6f)
                 + log_lognormal_(eta,    1.f, s0, 1e-6f)
                 + log_lognormal_(lsZ,    1.f, s0, 1e-6f)
                 + log_lognormal_(lsN,    1.f, s0, 1e-6f);
        float lq = log_normal_(beta, *qbm, spb, 1e-5f)
                 + log_lognormal_(sigma2, *qsm, sps, 1e-6f)
                 + log_lognormal_(eta,    *qem, spe, 1e-6f)
                 + log_lognormal_(lsZ,    *qzm, spz, 1e-6f)
                 + log_lognormal_(lsN,    *qnm, spn, 1e-6f);
        scal[0] = beta; scal[1] = sigma2; scal[2] = eta;
        scal[3] = lsZ;  scal[4] = lsN;    scal[5] = lp - lq;
        scal[6] = 0.f;
    }
    __syncthreads();
    const float beta = scal[0], sigma2 = scal[1], eta = scal[2];

    // ---- stage scaled x into smem (front of plane region; dead after build) ----
    {
        float lsZ = scal[3], lsN = scal[4];
        for (int i = tid; i < NN; i += NTH) {
            sm[i]      = x[2 * i]     / lsZ;
            sm[NN + i] = x[2 * i + 1] / lsN;
        }
    }
    __syncthreads();

    // ---- build lower-triangular cov, rows split by parity ----
    {
        const float* xs0 = sm;
        const float* xs1 = sm + NN;
        for (int it = tid; it < NN / 2; it += NTH) {
            int i = 2 * it + rank;
            float xi0 = xs0[i], xi1 = xs1[i];
            float* row = cov + (size_t)i * LDA;
            int j4 = i & ~3;
            for (int j = 0; j < j4; j += 4) {
                float4 a0 = *(const float4*)(xs0 + j);
                float4 a1 = *(const float4*)(xs1 + j);
                float4 o; float d0, d1;
                d0 = xi0 - a0.x; d1 = xi1 - a1.x; o.x = eta * __expf(-0.5f * (d0*d0 + d1*d1));
                d0 = xi0 - a0.y; d1 = xi1 - a1.y; o.y = eta * __expf(-0.5f * (d0*d0 + d1*d1));
                d0 = xi0 - a0.z; d1 = xi1 - a1.z; o.z = eta * __expf(-0.5f * (d0*d0 + d1*d1));
                d0 = xi0 - a0.w; d1 = xi1 - a1.w; o.w = eta * __expf(-0.5f * (d0*d0 + d1*d1));
                *(float4*)(row + j) = o;
            }
            for (int j = j4; j < i; ++j) {
                float d0 = xi0 - xs0[j], d1 = xi1 - xs1[j];
                row[j] = eta * __expf(-0.5f * (d0 * d0 + d1 * d1));
            }
            row[i] = eta + sigma2;
        }
    }
    cluster_sync_();

    // ---- blocked Cholesky, NB=32, HMMA trailing update ----
    for (int kb = 0; kb < 32; ++kb) {
        const int k0 = kb * 32;
        const int nt = NN - k0 - 32;    // always multiple of 32

        // phase A: load raw diag into Lkk; panel threads prefetch 2 rows
        {
            int r = wid, c = lane;
            Lkk[r * 33 + c] = (c <= r) ? cov[(size_t)(k0 + r) * LDA + k0 + c] : 0.f;
            int idx2 = tid + 512;
            int r2 = idx2 >> 5, c2 = idx2 & 31;
            Lkk[r2 * 33 + c2] = (c2 <= r2) ? cov[(size_t)(k0 + r2) * LDA + k0 + c2] : 0.f;
        }
        float a1[32], a2[32];
        const int tp = tid - 32;
        int it1 = tp, it2 = tp + 480;
        bool v1 = (tid >= 32) && (it1 < nt);
        bool v2 = (tid >= 32) && (it2 < nt);
        if (v1) {
            const float* rr = cov + (size_t)(k0 + 32 + it1) * LDA + k0;
            #pragma unroll
            for (int w = 0; w < 8; ++w) {
                float4 q = ((const float4*)rr)[w];
                a1[4*w] = q.x; a1[4*w+1] = q.y; a1[4*w+2] = q.z; a1[4*w+3] = q.w;
            }
        }
        if (v2) {
            const float* rr = cov + (size_t)(k0 + 32 + it2) * LDA + k0;
            #pragma unroll
            for (int w = 0; w < 8; ++w) {
                float4 q = ((const float4*)rr)[w];
                a2[4*w] = q.x; a2[4*w+1] = q.y; a2[4*w+2] = q.z; a2[4*w+3] = q.w;
            }
        }
        __syncthreads();

        // phase B: warp 0 factors the 32x32 diag block
        if (tid < 32) {
            float a[32];
            #pragma unroll
            for (int j = 0; j < 32; ++j) a[j] = Lkk[lane * 33 + j];
            #pragma unroll
            for (int j = 0; j < 32; ++j) {
                float dj = __shfl_sync(0xffffffffu, a[j], j);
                float sj = sqrtf(dj);
                float lrj = (lane == j) ? sj : a[j] / sj;
                a[j] = lrj;
                #pragma unroll
                for (int c = j + 1; c < 32; ++c) {
                    float lcj = __shfl_sync(0xffffffffu, lrj, c);
                    a[c] -= lrj * lcj;
                }
            }
            #pragma unroll
            for (int j = 0; j < 32; ++j)
                if (j <= lane) Lkk[lane * 33 + j] = a[j];
            rinv[lane] = 1.f / a[lane];
            float ld = logf(a[lane]);
            #pragma unroll
            for (int o = 16; o; o >>= 1) ld += __shfl_xor_sync(0xffffffffu, ld, o);
            if (lane == 0) scal[6] += ld;
        }
        __syncthreads();

        // phase C: diag writeback (rank0/warp0); panel solve redundant in both CTAs
        if (tid < 32) {
            if (rank == 0) {
                float* wr = cov + (size_t)(k0 + lane) * LDA + k0;
                for (int j = 0; j <= lane; ++j) wr[j] = Lkk[lane * 33 + j];
            }
        } else {
            if (v1 && v2) {
                #pragma unroll
                for (int j = 0; j < 32; ++j) {
                    float s1 = a1[j], s2 = a2[j];
                    #pragma unroll
                    for (int p = 0; p < j; ++p) {
                        float l = Lkk[j * 33 + p];
                        s1 -= a1[p] * l; s2 -= a2[p] * l;
                    }
                    float rj = rinv[j];
                    a1[j] = s1 * rj; a2[j] = s2 * rj;
                }
            } else if (v1) {
                trsm_row(a1, Lkk, rinv);
            }
            if (v1) {
                panel_store_row(Hb, Lb, it1, a1);
                if ((it1 & 1) == rank) {
                    float* wr = cov + (size_t)(k0 + 32 + it1) * LDA + k0;
                    #pragma unroll
                    for (int w = 0; w < 8; ++w)
                        ((float4*)wr)[w] = make_float4(a1[4*w], a1[4*w+1], a1[4*w+2], a1[4*w+3]);
                }
            }
            if (v2) {
                panel_store_row(Hb, Lb, it2, a2);
                if ((it2 & 1) == rank) {
                    float* wr = cov + (size_t)(k0 + 32 + it2) * LDA + k0;
                    #pragma unroll
                    for (int w = 0; w < 8; ++w)
                        ((float4*)wr)[w] = make_float4(a2[4*w], a2[4*w+1], a2[4*w+2], a2[4*w+3]);
                }
            }
            // leftover rows (kb==0: 992 rows > 960)
            int it3 = tp + 960;
            if (tid < 64 && it3 < nt) {
                const float* rr = cov + (size_t)(k0 + 32 + it3) * LDA + k0;
                #pragma unroll
                for (int w = 0; w < 8; ++w) {
                    float4 q = ((const float4*)rr)[w];
                    a1[4*w] = q.x; a1[4*w+1] = q.y; a1[4*w+2] = q.z; a1[4*w+3] = q.w;
                }
                trsm_row(a1, Lkk, rinv);
                panel_store_row(Hb, Lb, it3, a1);
                if ((it3 & 1) == rank) {
                    float* wr = cov + (size_t)(k0 + 32 + it3) * LDA + k0;
                    #pragma unroll
                    for (int w = 0; w < 8; ++w)
                        ((float4*)wr)[w] = make_float4(a1[4*w], a1[4*w+1], a1[4*w+2], a1[4*w+3]);
                }
            }
        }
        __syncthreads();

        // phase D: trailing SYRK via HMMA, 32 warp-workers across the cluster
        if (nt > 0) {
            const int ntile = nt >> 5;
            const int npair = ntile * (ntile + 1) / 2;
            const int worker = rank * 16 + wid;
            const int g = lane >> 2, t = lane & 3;
            const int g0 = k0 + 32;

            for (int pair = worker; pair < npair; pair += 32) {
                int tjb = 0, rem = pair;
                while (rem >= ntile - tjb) { rem -= ntile - tjb; ++tjb; }
                int tib = tjb + rem;
                const int i0 = tib * 32, j0 = tjb * 32;

                float c[2][4][4];
                #pragma unroll
                for (int mb = 0; mb < 2; ++mb)
                    #pragma unroll
                    for (int nb = 0; nb < 4; ++nb)
                        #pragma unroll
                        for (int q = 0; q < 4; ++q) c[mb][nb][q] = 0.f;

                #pragma unroll
                for (int kc = 0; kc < 32; kc += 16) {
                    uint32_t aH[2][4], aL[2][4], bH[4][2], bL[4][2];
                    #pragma unroll
                    for (int mb = 0; mb < 2; ++mb) {
                        int r0 = i0 + mb * 16 + g;
                        const uint16_t* h0p = Hb + r0 * PH + kc + t * 2;
                        const uint16_t* h8p = Hb + (r0 + 8) * PH + kc + t * 2;
                        const uint16_t* l0p = Lb + r0 * PH + kc + t * 2;
                        const uint16_t* l8p = Lb + (r0 + 8) * PH + kc + t * 2;
                        aH[mb][0] = *(const uint32_t*)h0p;
                        aH[mb][1] = *(const uint32_t*)h8p;
                        aH[mb][2] = *(const uint32_t*)(h0p + 8);
                        aH[mb][3] = *(const uint32_t*)(h8p + 8);
                        aL[mb][0] = *(const uint32_t*)l0p;
                        aL[mb][1] = *(const uint32_t*)l8p;
                        aL[mb][2] = *(const uint32_t*)(l0p + 8);
                        aL[mb][3] = *(const uint32_t*)(l8p + 8);
                    }
                    #pragma unroll
                    for (int nb = 0; nb < 4; ++nb) {
                        int rj = j0 + nb * 8 + g;
                        const uint16_t* hp = Hb + rj * PH + kc + t * 2;
                        const uint16_t* lp = Lb + rj * PH + kc + t * 2;
                        bH[nb][0] = *(const uint32_t*)hp;
                        bH[nb][1] = *(const uint32_t*)(hp + 8);
                        bL[nb][0] = *(const uint32_t*)lp;
                        bL[nb][1] = *(const uint32_t*)(lp + 8);
                    }
                    #pragma unroll
                    for (int mb = 0; mb < 2; ++mb)
                        #pragma unroll
                        for (int nb = 0; nb < 4; ++nb) {
                            hmma(c[mb][nb], aH[mb], bH[nb]);
                            hmma(c[mb][nb], aH[mb], bL[nb]);
                            hmma(c[mb][nb], aL[mb], bH[nb]);
                        }
                }

                // epilogue: RMW cov (lower triangle only)
                #pragma unroll
                for (int mb = 0; mb < 2; ++mb) {
                    #pragma unroll
                    for (int half = 0; half < 2; ++half) {
                        int i_loc = i0 + mb * 16 + g + half * 8;
                        if (i_loc < nt) {
                            float* row = cov + (size_t)(g0 + i_loc) * LDA + g0;
                            #pragma unroll
                            for (int nb = 0; nb < 4; ++nb) {
                                int j = j0 + nb * 8 + t * 2;
                                float cx = c[mb][nb][half * 2];
                                float cy = c[mb][nb][half * 2 + 1];
                                if (j + 1 <= i_loc) {
                                    float2 v = *(float2*)(row + j);
                                    v.x -= cx; v.y -= cy;
                                    *(float2*)(row + j) = v;
                                } else if (j <= i_loc) {
                                    row[j] -= cx;
                                }
                            }
                        }
                    }
                }
            }
        }
        cluster_sync_();
    }

    // ---- forward substitution + output: rank 0 only ----
    if (rank != 0) return;

    float* rhs = sm;   // reuse plane region
    for (int i = tid; i < NN; i += NTH) rhs[i] = y[i] - beta;
    __syncthreads();

    for (int kb = 0; kb < 32; ++kb) {
        const int k0 = kb * 32;
        if (tid < 32) {
            const float* lrow = cov + (size_t)(k0 + lane) * LDA + k0;
            float lr[32];
            #pragma unroll
            for (int w = 0; w < 8; ++w) {
                float4 q = ((const float4*)lrow)[w];
                lr[4*w] = q.x; lr[4*w+1] = q.y; lr[4*w+2] = q.z; lr[4*w+3] = q.w;
            }
            float t = rhs[k0 + lane];
            #pragma unroll
            for (int j = 0; j < 32; ++j) {
                if (lane == j) t /= lr[j];
                float sj = __shfl_sync(0xffffffffu, t, j);
                if (lane > j) t -= sj * lr[j];
            }
            rhs[k0 + lane] = t;
        }
        __syncthreads();
        for (int i = k0 + 32 + tid; i < NN; i += NTH) {
            const float* row = cov + (size_t)i * LDA + k0;
            float acc = 0.f;
            #pragma unroll
            for (int w = 0; w < 8; ++w) {
                float4 c4 = ((const float4*)row)[w];
                acc += c4.x * rhs[k0 + 4*w]     + c4.y * rhs[k0 + 4*w + 1]
                     + c4.z * rhs[k0 + 4*w + 2] + c4.w * rhs[k0 + 4*w + 3];
            }
            rhs[i] -= acc;
        }
        __syncthreads();
    }

    float q = 0.f;
    for (int i = tid; i < NN; i += NTH) { float v = rhs[i]; q += v * v; }
    red[tid] = q;
    __syncthreads();
    for (int s = NTH / 2; s; s >>= 1) {
        if (tid < s) red[tid] += red[tid + s];
        __syncthreads();
    }
    if (tid == 0) {
        float logdet = 2.f * scal[6];
        const float LN2PI = 1.8378770664093453f;
        out[m] = -0.5f * (red[0] + logdet + 1024.f * LN2PI) + scal[5];
    }
}

extern "C" void kernel_launch(void* const* d_in, const int* in_sizes, int n_in,
                              void* d_out, int out_size)
{
    (void)in_sizes; (void)n_in; (void)out_size;
    const int smem_bytes = SMEM_FLOATS * (int)sizeof(float);
    cudaFuncSetAttribute(vi_kernel, cudaFuncAttributeMaxDynamicSharedMemorySize, smem_bytes);

    vi_kernel<<<2 * MM, NTH, smem_bytes>>>(
        (const float*)d_in[0], (const float*)d_in[1], (const float*)d_in[2],
        (const float*)d_in[3], (const float*)d_in[4],
        (const float*)d_in[5], (const float*)d_in[6],
        (const float*)d_in[7], (const float*)d_in[8],
        (const float*)d_in[9], (const float*)d_in[10],
        (const float*)d_in[11], (const float*)d_in[12],
        (float*)d_out);
}